// round 1
// baseline (speedup 1.0000x reference)
#include <cuda_runtime.h>
#include <cstdint>

#define KCB   8192          // codebook vectors
#define DCB   256           // latent dim
#define NROWS 16384         // 16*32*32 latent vectors
#define OUTN  4194304       // 16*256*32*32 output elements

#define BM 64               // rows per block
#define BN 128              // codebook cols per chunk
#define BSTR 132            // padded k-stride of B smem tile
#define LOSS_BLOCKS 1024

// ---- device scratch (no allocations allowed) ----
__device__ float  g_zz[NROWS];
__device__ float  g_ee[KCB];
__device__ int    g_idx[NROWS];
__device__ double g_part[LOSS_BLOCKS];

// ------------------------------------------------------------------
// ee[k] = sum_d emb[k][d]^2   (order-robust: enters at ~1e-6 scale,
// rounding differences ~1e-12 are irrelevant to the argmin)
// ------------------------------------------------------------------
__global__ void ee_kernel(const float* __restrict__ emb) {
    int warp = (blockIdx.x * blockDim.x + threadIdx.x) >> 5;
    int lane = threadIdx.x & 31;
    if (warp >= KCB) return;
    const float* e = emb + (size_t)warp * DCB;
    float s = 0.f;
#pragma unroll
    for (int j = 0; j < 8; ++j) {
        float v = e[lane + j * 32];
        s = __fadd_rn(s, __fmul_rn(v, v));
    }
#pragma unroll
    for (int o = 16; o; o >>= 1) s = __fadd_rn(s, __shfl_down_sync(0xffffffffu, s, o));
    if (lane == 0) g_ee[warp] = s;
}

// ------------------------------------------------------------------
// zz[n] = sum_d z[n][d]^2, SEQUENTIAL fp32 order (guess at reference's
// reduction order; its low bits decide boundary-straddle rows).
// z layout (b,d,h,w): element (n,d) at  b*262144 + d*1024 + hw.
// Consecutive threads read consecutive addresses each step -> coalesced.
// ------------------------------------------------------------------
__global__ void zz_kernel(const float* __restrict__ z) {
    int n = blockIdx.x * blockDim.x + threadIdx.x;
    if (n >= NROWS) return;
    const float* p = z + (size_t)(n >> 10) * 262144 + (n & 1023);
    float s = 0.f;
    for (int d = 0; d < DCB; ++d) {
        float v = p[(size_t)d * 1024];
        s = __fadd_rn(s, __fmul_rn(v, v));
    }
    g_zz[n] = s;
}

// ------------------------------------------------------------------
// Fused GEMM + argmin.
// Block: 256 threads = (tx 0..31) x (ty 0..7). ty owns rows ty*8..ty*8+7
// (so each row's candidates live in exactly one warp -> shuffle reduce).
// A (64 rows x 256 d) resident in smem for the whole block.
// B (128 k x 32 d) staged per d-step. acc: 8x4 per thread.
// s = fl( fl(zz+ee) - 2*dot )  -- replicates reference fp32 rounding.
// ------------------------------------------------------------------
__global__ __launch_bounds__(256, 2)
void argmin_kernel(const float* __restrict__ z, const float* __restrict__ emb) {
    extern __shared__ float smem[];
    float* As = smem;               // [256][64]
    float* Bs = smem + DCB * BM;    // [32][BSTR]

    int tid = threadIdx.x;
    int tx = tid & 31, ty = tid >> 5;
    int row0 = blockIdx.x * BM;
    const float* zbase = z + (size_t)(row0 >> 10) * 262144 + (row0 & 1023);

    // Load A tile once: (d, n) from global, coalesced along n.
#pragma unroll
    for (int it = 0; it < 16; ++it) {
        int lin = it * 256 + tid;
        int d = lin >> 4;
        int n4 = (lin & 15) << 2;
        float4 v = *reinterpret_cast<const float4*>(zbase + (size_t)d * 1024 + n4);
        *reinterpret_cast<float4*>(&As[d * BM + n4]) = v;
    }

    float zzr[8];
#pragma unroll
    for (int i = 0; i < 8; ++i) zzr[i] = g_zz[row0 + ty * 8 + i];

    float bestS[8];
    int   bestK[8];
#pragma unroll
    for (int i = 0; i < 8; ++i) { bestS[i] = __int_as_float(0x7f800000); bestK[i] = 0; }

    for (int kc = 0; kc < KCB / BN; ++kc) {
        int k0c = kc * BN;
        float acc[8][4];
#pragma unroll
        for (int i = 0; i < 8; ++i)
#pragma unroll
            for (int j = 0; j < 4; ++j) acc[i][j] = 0.f;

        for (int ds = 0; ds < DCB / 32; ++ds) {
            __syncthreads();
            // stage B: 128 k x 32 d, stored transposed Bs[d][k]
            int ksub = tid >> 3;
            int f4 = (tid & 7) << 2;
#pragma unroll
            for (int p = 0; p < 4; ++p) {
                int kk = ksub + p * 32;
                float4 v = *reinterpret_cast<const float4*>(
                    emb + (size_t)(k0c + kk) * DCB + ds * 32 + f4);
                Bs[(f4 + 0) * BSTR + kk] = v.x;
                Bs[(f4 + 1) * BSTR + kk] = v.y;
                Bs[(f4 + 2) * BSTR + kk] = v.z;
                Bs[(f4 + 3) * BSTR + kk] = v.w;
            }
            __syncthreads();
#pragma unroll
            for (int d = 0; d < 32; ++d) {
                const float* arow = &As[(ds * 32 + d) * BM + ty * 8];
                float4 a0 = *reinterpret_cast<const float4*>(arow);
                float4 a1 = *reinterpret_cast<const float4*>(arow + 4);
                float4 bv = *reinterpret_cast<const float4*>(&Bs[d * BSTR + tx * 4]);
                float a[8] = {a0.x, a0.y, a0.z, a0.w, a1.x, a1.y, a1.z, a1.w};
                float bb[4] = {bv.x, bv.y, bv.z, bv.w};
#pragma unroll
                for (int i = 0; i < 8; ++i)
#pragma unroll
                    for (int j = 0; j < 4; ++j)
                        acc[i][j] = fmaf(a[i], bb[j], acc[i][j]);
            }
        }
        // epilogue: scores + running argmin (per-thread k scan is ascending,
        // so strict '<' keeps the earliest/lowest index on ties)
#pragma unroll
        for (int j = 0; j < 4; ++j) {
            int kk = k0c + tx * 4 + j;
            float eek = g_ee[kk];
#pragma unroll
            for (int i = 0; i < 8; ++i) {
                float t = __fadd_rn(zzr[i], eek);                       // fl(zz+ee)
                float s = __fadd_rn(t, __fmul_rn(-2.0f, acc[i][j]));    // fl(t-2*dot)
                if (s < bestS[i]) { bestS[i] = s; bestK[i] = kk; }
            }
        }
    }

    // final reduce across the 32 lanes of this row-group's warp, with
    // exact tie-break to the lowest index (matches jnp.argmin)
#pragma unroll
    for (int i = 0; i < 8; ++i) {
        float s = bestS[i]; int k = bestK[i];
#pragma unroll
        for (int o = 16; o; o >>= 1) {
            float s2 = __shfl_xor_sync(0xffffffffu, s, o);
            int   k2 = __shfl_xor_sync(0xffffffffu, k, o);
            if (s2 < s || (s2 == s && k2 < k)) { s = s2; k = k2; }
        }
        if (tx == 0) g_idx[row0 + ty * 8 + i] = k;
    }
}

// ------------------------------------------------------------------
// out[i] = emb[idx[n]][d]  (out has the same (b,d,h,w) layout as z)
// plus deterministic fp64 partial sums of (e - z)^2 per block.
// Fixed grid + fixed grid-stride order + smem tree => deterministic.
// ------------------------------------------------------------------
__global__ void out_kernel(const float* __restrict__ z,
                           const float* __restrict__ emb,
                           float* __restrict__ out) {
    __shared__ double sh[256];
    double acc = 0.0;
    int stride = gridDim.x * blockDim.x;
    for (int i = blockIdx.x * blockDim.x + threadIdx.x; i < OUTN; i += stride) {
        int hw = i & 1023;
        int d = (i >> 10) & 255;
        int b = i >> 18;
        int n = b * 1024 + hw;
        float e = emb[(size_t)g_idx[n] * DCB + d];
        out[i] = e;
        float diff = __fadd_rn(e, -z[i]);
        acc += (double)diff * (double)diff;
    }
    sh[threadIdx.x] = acc;
    __syncthreads();
    for (int o = 128; o; o >>= 1) {
        if (threadIdx.x < o) sh[threadIdx.x] += sh[threadIdx.x + o];
        __syncthreads();
    }
    if (threadIdx.x == 0) g_part[blockIdx.x] = sh[0];
}

__global__ void fin_kernel(float* __restrict__ out, int out_size) {
    if (out_size <= OUTN) return;   // loss slot not present
    double t = 0.0;
    for (int i = 0; i < LOSS_BLOCKS; ++i) t += g_part[i];
    float m = (float)(t / (double)OUTN);
    // reference: mean1 + 0.25*mean2 with mean1 == mean2 numerically
    out[OUTN] = __fadd_rn(m, __fmul_rn(0.25f, m));
}

// ------------------------------------------------------------------
extern "C" void kernel_launch(void* const* d_in, const int* in_sizes, int n_in,
                              void* d_out, int out_size) {
    const float* z   = (const float*)d_in[0];
    const float* emb = (const float*)d_in[1];
    if (n_in >= 2 && in_sizes[0] == KCB * DCB && in_sizes[1] == OUTN) {
        // defensive: swapped input order
        z   = (const float*)d_in[1];
        emb = (const float*)d_in[0];
    }
    float* out = (float*)d_out;

    static const int SMEM_BYTES = (DCB * BM + 32 * BSTR) * (int)sizeof(float); // 82432
    cudaFuncSetAttribute(argmin_kernel,
                         cudaFuncAttributeMaxDynamicSharedMemorySize, SMEM_BYTES);

    ee_kernel<<<KCB / 8, 256>>>(emb);
    zz_kernel<<<NROWS / 256, 256>>>(z);
    argmin_kernel<<<NROWS / BM, 256, SMEM_BYTES>>>(z, emb);
    out_kernel<<<LOSS_BLOCKS, 256>>>(z, emb, out);
    fin_kernel<<<1, 1>>>(out, out_size);
}